// round 6
// baseline (speedup 1.0000x reference)
#include <cuda_runtime.h>
#include <cuda_bf16.h>
#include <cstdint>
#include <math.h>

// Problem constants
#define NN 262144
#define EE 524288
#define GG 8192
#define DD 300
#define DD2 600
#define LL 5
#define HGC 2348
#define H1 1200
#define NT 128

// ---------------- scratch (device globals) ----------------
__device__ float g_h  [(size_t)NN * DD];
__device__ float g_hl [(size_t)NN * DD];
__device__ float g_acc[(size_t)NN * DD];
__device__ float g_y1 [(size_t)NN * DD2];
__device__ float g_y2 [(size_t)NN * DD];
__device__ float g_vn [(size_t)GG * DD];
__device__ float g_vt [(size_t)GG * DD];
__device__ float g_u1 [(size_t)GG * DD2];
__device__ float g_u2 [(size_t)GG * DD];
__device__ float g_hg [(size_t)GG * HGC];
__device__ float g_t1 [(size_t)GG * H1];
__device__ float g_stats[2 * DD2];
__device__ float g_scale[DD2];
__device__ float g_shift[DD2];

// pre-split transposed weights: [N, Kpad] bf16 hi / lo
#define BT_TOTAL 6453248
__device__ __nv_bfloat16 g_bth[BT_TOTAL];
__device__ __nv_bfloat16 g_btl[BT_TOTAL];

// ---------------- helpers ----------------
__device__ __forceinline__ uint32_t smem_u32(const void* p) {
    uint32_t a;
    asm("{ .reg .u64 t; cvta.to.shared.u64 t, %1; cvt.u32.u64 %0, t; }" : "=r"(a) : "l"(p));
    return a;
}

__device__ __forceinline__ uint32_t packbf2(float a, float b) {
    __nv_bfloat162 t = __floats2bfloat162_rn(a, b);
    return *reinterpret_cast<uint32_t*>(&t);
}
__device__ __forceinline__ float bf_hi(float x) {
    return __bfloat162float(__float2bfloat16_rn(x));
}
__device__ __forceinline__ float gelu_tanh(float x) {
    const float k0 = 0.7978845608028654f;
    const float k1 = 0.044715f;
    float x3 = x * x * x;
    return 0.5f * x * (1.f + tanhf(k0 * (x + k1 * x3)));
}

__device__ __forceinline__ void mma_bf16(float* d, const uint32_t* a, const uint32_t* b) {
    asm volatile(
        "mma.sync.aligned.m16n8k16.row.col.f32.bf16.bf16.f32 "
        "{%0,%1,%2,%3}, {%4,%5,%6,%7}, {%8,%9}, {%0,%1,%2,%3};\n"
        : "+f"(d[0]), "+f"(d[1]), "+f"(d[2]), "+f"(d[3])
        : "r"(a[0]), "r"(a[1]), "r"(a[2]), "r"(a[3]),
          "r"(b[0]), "r"(b[1]));
}

__device__ __forceinline__ void ldsm_x4(uint32_t& r0, uint32_t& r1, uint32_t& r2,
                                        uint32_t& r3, uint32_t addr) {
    asm volatile("ldmatrix.sync.aligned.m8n8.x4.shared.b16 {%0,%1,%2,%3}, [%4];"
                 : "=r"(r0), "=r"(r1), "=r"(r2), "=r"(r3) : "r"(addr));
}

// ---------------- utility kernels ----------------
__global__ void k_zero(float* p, size_t n) {
    size_t i = (size_t)blockIdx.x * blockDim.x + threadIdx.x;
    if (i < n) p[i] = 0.f;
}

__global__ void k_embed(const int* __restrict__ x_atom,
                        const float* __restrict__ atom_emb,
                        float* __restrict__ h) {
    size_t idx4 = (size_t)blockIdx.x * blockDim.x + threadIdx.x;
    size_t tot4 = (size_t)NN * DD / 4;
    if (idx4 >= tot4) return;
    int i  = (int)(idx4 / (DD / 4));
    int c4 = (int)(idx4 - (size_t)i * (DD / 4));
    const float4* srcv = (const float4*)(atom_emb + (size_t)x_atom[i] * DD);
    ((float4*)h)[idx4] = srcv[c4];
}

__global__ void k_hl_acc(const float* __restrict__ h,
                         const float* __restrict__ vn,
                         const int* __restrict__ batch,
                         const float* __restrict__ eps, int l,
                         float* __restrict__ hl,
                         float* __restrict__ acc) {
    size_t idx4 = (size_t)blockIdx.x * blockDim.x + threadIdx.x;
    size_t tot4 = (size_t)NN * DD / 4;
    if (idx4 >= tot4) return;
    int i  = (int)(idx4 / (DD / 4));
    int c4 = (int)(idx4 - (size_t)i * (DD / 4));
    int b  = batch[i];
    float e = 1.f + eps[l];
    float4 hv = ((const float4*)h)[idx4];
    float4 vv = ((const float4*)(vn + (size_t)b * DD))[c4];
    float4 o, a;
    o.x = hv.x + vv.x; o.y = hv.y + vv.y; o.z = hv.z + vv.z; o.w = hv.w + vv.w;
    a.x = e * o.x; a.y = e * o.y; a.z = e * o.z; a.w = e * o.w;
    ((float4*)hl)[idx4] = o;
    ((float4*)acc)[idx4] = a;
}

__global__ void k_edge(const float* __restrict__ hl,
                       const float* __restrict__ eemb,
                       const int* __restrict__ src,
                       const int* __restrict__ dst,
                       const int* __restrict__ eattr,
                       float* __restrict__ acc) {
    int sub = threadIdx.x / 75;
    int c4  = threadIdx.x % 75;
    int e = blockIdx.x * 4 + sub;
    int s = src[e], d = dst[e], a = eattr[e];
    float4 hv = *(const float4*)(hl   + (size_t)s * DD + c4 * 4);
    float4 ev = *(const float4*)(eemb + (size_t)a * DD + c4 * 4);
    float* out = acc + (size_t)d * DD + c4 * 4;
    float m;
    m = hv.x + ev.x; if (m > 0.f) atomicAdd(out + 0, m);
    m = hv.y + ev.y; if (m > 0.f) atomicAdd(out + 1, m);
    m = hv.z + ev.z; if (m > 0.f) atomicAdd(out + 2, m);
    m = hv.w + ev.w; if (m > 0.f) atomicAdd(out + 3, m);
}

__device__ __forceinline__ int lbound(const int* __restrict__ arr, int n, int val) {
    int lo = 0, hi = n;
    while (lo < hi) { int mid = (lo + hi) >> 1; if (arr[mid] < val) lo = mid + 1; else hi = mid; }
    return lo;
}

__global__ void k_vt(const float* __restrict__ hl, const int* __restrict__ batch,
                     const float* __restrict__ vn, float* __restrict__ vt) {
    int g = blockIdx.x;
    __shared__ int ss, se;
    if (threadIdx.x == 0) { ss = lbound(batch, NN, g); se = lbound(batch, NN, g + 1); }
    __syncthreads();
    int s0 = ss, s1 = se;
    for (int c = threadIdx.x; c < DD; c += blockDim.x) {
        float s = vn[(size_t)g * DD + c];
        for (int r = s0; r < s1; r++) s += hl[(size_t)r * DD + c];
        vt[(size_t)g * DD + c] = s;
    }
}

__global__ void k_pool(const float* __restrict__ h, const int* __restrict__ batch,
                       const float* __restrict__ fp, float* __restrict__ hg) {
    int g = blockIdx.x;
    __shared__ int ss, se;
    if (threadIdx.x == 0) { ss = lbound(batch, NN, g); se = lbound(batch, NN, g + 1); }
    __syncthreads();
    int s0 = ss, s1 = se;
    for (int c = threadIdx.x; c < HGC; c += blockDim.x) {
        float v;
        if (c < DD) {
            v = 0.f;
            for (int r = s0; r < s1; r++) v += h[(size_t)r * DD + c];
        } else {
            v = fp[(size_t)g * 2048 + (c - DD)];
        }
        hg[(size_t)g * HGC + c] = v;
    }
}

__global__ void k_bnfinal(const float* __restrict__ stats,
                          const float* __restrict__ gamma,
                          const float* __restrict__ beta,
                          int M, int C,
                          float* __restrict__ scale, float* __restrict__ shift) {
    int c = blockIdx.x * blockDim.x + threadIdx.x;
    if (c >= C) return;
    float inv = 1.f / (float)M;
    float mean = stats[c] * inv;
    float var  = stats[C + c] * inv - mean * mean;
    float s = gamma[c] * rsqrtf(var + 1e-5f);
    scale[c] = s;
    shift[c] = beta[c] - mean * s;
}

__global__ void k_bnapply(const float* __restrict__ X, float* __restrict__ Y,
                          size_t total4, int C4,
                          const float* __restrict__ scale,
                          const float* __restrict__ shift, int relu) {
    size_t idx4 = (size_t)blockIdx.x * blockDim.x + threadIdx.x;
    if (idx4 >= total4) return;
    int c4 = (int)(idx4 % C4) * 4;
    float4 x = ((const float4*)X)[idx4];
    float4 o;
    o.x = x.x * scale[c4 + 0] + shift[c4 + 0];
    o.y = x.y * scale[c4 + 1] + shift[c4 + 1];
    o.z = x.z * scale[c4 + 2] + shift[c4 + 2];
    o.w = x.w * scale[c4 + 3] + shift[c4 + 3];
    if (relu) {
        o.x = fmaxf(o.x, 0.f); o.y = fmaxf(o.y, 0.f);
        o.z = fmaxf(o.z, 0.f); o.w = fmaxf(o.w, 0.f);
    }
    ((float4*)Y)[idx4] = o;
}

// Transpose + split weights: W[K,N] fp32 -> BTH/BTL[n*Kpad + k] bf16 (zero-padded)
__global__ void k_split_w(const float* __restrict__ W, int K, int N, int Kpad,
                          __nv_bfloat16* __restrict__ bth,
                          __nv_bfloat16* __restrict__ btl) {
    __shared__ float tile[32][33];
    int nb = blockIdx.x * 32, kb = blockIdx.y * 32;
    int tx = threadIdx.x, ty = threadIdx.y;
    for (int i = ty; i < 32; i += 8) {
        int k = kb + i, n = nb + tx;
        tile[i][tx] = (k < K && n < N) ? W[(size_t)k * N + n] : 0.f;
    }
    __syncthreads();
    for (int i = ty; i < 32; i += 8) {
        int n = nb + i, k = kb + tx;
        if (n < N && k < Kpad) {
            float v = tile[tx][i];
            float h = bf_hi(v);
            bth[(size_t)n * Kpad + k] = __float2bfloat16_rn(h);
            btl[(size_t)n * Kpad + k] = __float2bfloat16_rn(v - h);
        }
    }
}

// ---------------- bf16x3 mma.sync GEMM with ldmatrix ----------------
// C[M,N] = act( A'[M,K] @ BT^T + bias ), A' optionally relu(A*scaleA[k]+shiftA[k])
// BT pre-transposed [N,Kpad] split bf16. M % 128 == 0. CTA tile 128x128,
// 8 warps of 64x32. Double-buffered 32-k stages; hi|lo interleaved in 128B rows.
// Optional column sum/sumsq of pre-activation C into stats[0:N), stats[N:2N).

#define SM2_BYTES (1024 + 65536)

__global__ __launch_bounds__(256, 1)
void k_mma2(int M, int N, int Kreal, int NS,
            const float* __restrict__ A,
            const __nv_bfloat16* __restrict__ BTH,
            const __nv_bfloat16* __restrict__ BTL, int Kpad,
            const float* __restrict__ bias, float* __restrict__ C,
            const float* __restrict__ aScale, const float* __restrict__ aShift,
            float* stats, int act) {
    extern __shared__ char dsm[];
    const uint32_t base = (smem_u32(dsm) + 1023u) & ~1023u;

    const int tid  = threadIdx.x;
    const int lane = tid & 31;
    const int warp = tid >> 5;
    const int warpM = warp >> 2;        // 0..1
    const int warpN = warp & 3;         // 0..3
    const int gID = lane >> 2;
    const int tg  = lane & 3;
    const int rowBase = blockIdx.y * 128;
    const int colBase = blockIdx.x * 128;
    const bool aT = (aScale != nullptr);

    // ldmatrix lane geometry
    const int laneRow = lane & 15;
    const uint32_t laneK16 = (uint32_t)((lane >> 4) * 16);
    const uint32_t xm = (uint32_t)((lane & 7) << 4);
    const uint32_t aRowOff = (uint32_t)((warpM * 64 + laneRow) * 128);
    const uint32_t bRowOff = (uint32_t)((warpN * 32 + laneRow) * 128);

    float acc[4][4][4];
    #pragma unroll
    for (int i = 0; i < 4; i++)
        #pragma unroll
        for (int j = 0; j < 4; j++)
            #pragma unroll
            for (int r = 0; r < 4; r++) acc[i][j][r] = 0.f;

    // staging regs
    float4 aV[4];
    uint4  bVH[2], bVL[2];

    auto loadStage = [&](int s) {
        int k0 = s * 32;
        #pragma unroll
        for (int i = 0; i < 4; i++) {
            int idx = tid + i * 256;
            int q = idx & 7;
            int gk = k0 + q * 4;
            float4 v = make_float4(0.f, 0.f, 0.f, 0.f);
            if (gk < Kreal) {
                int r = idx >> 3;
                v = *(const float4*)(A + (size_t)(rowBase + r) * Kreal + gk);
                if (aT) {
                    v.x = fmaxf(v.x * __ldg(aScale + gk + 0) + __ldg(aShift + gk + 0), 0.f);
                    v.y = fmaxf(v.y * __ldg(aScale + gk + 1) + __ldg(aShift + gk + 1), 0.f);
                    v.z = fmaxf(v.z * __ldg(aScale + gk + 2) + __ldg(aShift + gk + 2), 0.f);
                    v.w = fmaxf(v.w * __ldg(aScale + gk + 3) + __ldg(aShift + gk + 3), 0.f);
                }
            }
            aV[i] = v;
        }
        #pragma unroll
        for (int i = 0; i < 2; i++) {
            int idx = tid + i * 256;
            int r = idx >> 2, u = idx & 3;
            int gn = colBase + r;
            uint4 vh = make_uint4(0, 0, 0, 0), vl = make_uint4(0, 0, 0, 0);
            if (gn < N) {
                size_t o = (size_t)gn * Kpad + k0 + u * 8;
                vh = *(const uint4*)(BTH + o);
                vl = *(const uint4*)(BTL + o);
            }
            bVH[i] = vh; bVL[i] = vl;
        }
    };

    auto storeStage = [&](int buf) {
        uint32_t Ab = base + (uint32_t)buf * 32768u;
        uint32_t Bb = Ab + 16384u;
        #pragma unroll
        for (int i = 0; i < 4; i++) {
            int idx = tid + i * 256;
            int r = idx >> 3, q = idx & 7;
            float4 v = aV[i];
            float hx = bf_hi(v.x), hy = bf_hi(v.y), hz = bf_hi(v.z), hw = bf_hi(v.w);
            uint32_t h01 = packbf2(hx, hy), h23 = packbf2(hz, hw);
            uint32_t l01 = packbf2(v.x - hx, v.y - hy), l23 = packbf2(v.z - hz, v.w - hw);
            uint32_t addr = Ab + (uint32_t)(r * 128) + (((uint32_t)(q * 8)) ^ ((uint32_t)((r & 7) << 4)));
            asm volatile("st.shared.v2.b32 [%0], {%1,%2};" :: "r"(addr), "r"(h01), "r"(h23) : "memory");
            asm volatile("st.shared.v2.b32 [%0], {%1,%2};" :: "r"(addr ^ 64u), "r"(l01), "r"(l23) : "memory");
        }
        #pragma unroll
        for (int i = 0; i < 2; i++) {
            int idx = tid + i * 256;
            int r = idx >> 2, u = idx & 3;
            uint32_t addr = Bb + (uint32_t)(r * 128) + (((uint32_t)(u * 16)) ^ ((uint32_t)((r & 7) << 4)));
            uint4 vh = bVH[i], vl = bVL[i];
            asm volatile("st.shared.v4.b32 [%0], {%1,%2,%3,%4};"
                         :: "r"(addr), "r"(vh.x), "r"(vh.y), "r"(vh.z), "r"(vh.w) : "memory");
            asm volatile("st.shared.v4.b32 [%0], {%1,%2,%3,%4};"
                         :: "r"(addr ^ 64u), "r"(vl.x), "r"(vl.y), "r"(vl.z), "r"(vl.w) : "memory");
        }
    };

    auto compute = [&](int buf) {
        uint32_t Ab = base + (uint32_t)buf * 32768u;
        uint32_t Bb = Ab + 16384u;
        #pragma unroll
        for (int ks = 0; ks < 2; ks++) {
            uint32_t kSw = ((uint32_t)(ks * 32) + laneK16) ^ xm;
            uint32_t ah[4][4], al[4][4], bh[4][2], bl[4][2];
            #pragma unroll
            for (int mt = 0; mt < 4; mt++) {
                uint32_t ad = Ab + aRowOff + (uint32_t)(mt * 2048) + kSw;
                ldsm_x4(ah[mt][0], ah[mt][1], ah[mt][2], ah[mt][3], ad);
                ldsm_x4(al[mt][0], al[mt][1], al[mt][2], al[mt][3], ad ^ 64u);
            }
            #pragma unroll
            for (int ntp = 0; ntp < 2; ntp++) {
                uint32_t bd = Bb + bRowOff + (uint32_t)(ntp * 2048) + kSw;
                uint32_t r0, r1, r2, r3;
                ldsm_x4(r0, r1, r2, r3, bd);
                bh[2 * ntp][0] = r0; bh[2 * ntp + 1][0] = r1;
                bh[2 * ntp][1] = r2; bh[2 * ntp + 1][1] = r3;
                ldsm_x4(r0, r1, r2, r3, bd ^ 64u);
                bl[2 * ntp][0] = r0; bl[2 * ntp + 1][0] = r1;
                bl[2 * ntp][1] = r2; bl[2 * ntp + 1][1] = r3;
            }
            #pragma unroll
            for (int mt = 0; mt < 4; mt++)
                #pragma unroll
                for (int nt = 0; nt < 4; nt++)
                    mma_bf16(acc[mt][nt], ah[mt], bh[nt]);
            #pragma unroll
            for (int mt = 0; mt < 4; mt++)
                #pragma unroll
                for (int nt = 0; nt < 4; nt++)
                    mma_bf16(acc[mt][nt], ah[mt], bl[nt]);
            #pragma unroll
            for (int mt = 0; mt < 4; mt++)
                #pragma unroll
                for (int nt = 0; nt < 4; nt++)
                    mma_bf16(acc[mt][nt], al[mt], bh[nt]);
        }
    };

    loadStage(0);
    storeStage(0);
    __syncthreads();

    for (int s = 0; s < NS; s++) {
        int buf = s & 1;
        if (s + 1 < NS) loadStage(s + 1);
        compute(buf);
        if (s + 1 < NS) storeStage(buf ^ 1);
        __syncthreads();
    }

    // ---- epilogue ----
    const bool doStats = (stats != nullptr);
    float* sstat = reinterpret_cast<float*>(dsm);   // 256 floats scratch
    if (doStats) {
        if (tid < 256) sstat[tid] = 0.f;
        __syncthreads();
    }

    #pragma unroll
    for (int nt = 0; nt < 4; nt++) {
        #pragma unroll
        for (int p = 0; p < 2; p++) {
            int lc = warpN * 32 + nt * 8 + 2 * tg + p;
            int col = colBase + lc;
            bool cv = col < N;
            float bs = cv ? __ldg(bias + col) : 0.f;
            float s = 0.f, s2 = 0.f;
            #pragma unroll
            for (int mt = 0; mt < 4; mt++) {
                int row = rowBase + warpM * 64 + mt * 16 + gID;
                #pragma unroll
                for (int hh = 0; hh < 2; hh++) {
                    float v = acc[mt][nt][p + 2 * hh] + bs;
                    s += v; s2 += v * v;
                    float o = v;
                    if (act == 1) o = fmaxf(o, 0.f);
                    else if (act == 2) o = gelu_tanh(o);
                    if (cv) C[(size_t)(row + 8 * hh) * N + col] = o;
                }
            }
            if (doStats && cv) {
                atomicAdd(&sstat[lc], s);
                atomicAdd(&sstat[128 + lc], s2);
            }
        }
    }
    if (doStats) {
        __syncthreads();
        if (tid < 128) {
            int col = colBase + tid;
            if (col < N) {
                atomicAdd(&stats[col], sstat[tid]);
                atomicAdd(&stats[N + col], sstat[128 + tid]);
            }
        }
    }
}

// ---------------- host orchestration ----------------
static inline int cdiv(long long a, long long b) { return (int)((a + b - 1) / b); }

// BT offsets (elements)
#define KP1 320
#define KP2 640
#define KPH1 2368
#define KPH2 1216
static inline size_t offW1(int l)  { return (size_t)l * 192000; }
static inline size_t offW2(int l)  { return 960000 + (size_t)l * 192000; }
static inline size_t offVW1(int l) { return 1920000 + (size_t)l * 192000; }
static inline size_t offVW2(int l) { return 2688000 + (size_t)l * 192000; }
static inline size_t offPW1()      { return 3456000; }
static inline size_t offPW2()      { return 6297600; }

static void launch_split(const float* W, int K, int N, int Kpad,
                         __nv_bfloat16* bth, __nv_bfloat16* btl) {
    dim3 grid(cdiv(N, 32), cdiv(Kpad, 32));
    k_split_w<<<grid, dim3(32, 8)>>>(W, K, N, Kpad, bth, btl);
}

static void launch_mma2(int M, int N, int K, int Kpad, const float* A,
                        const __nv_bfloat16* bth, const __nv_bfloat16* btl,
                        const float* bias, float* C,
                        const float* aS, const float* aH, float* stats, int act) {
    static int attrSet = 0;
    if (!attrSet) {
        cudaFuncSetAttribute(k_mma2, cudaFuncAttributeMaxDynamicSharedMemorySize, SM2_BYTES);
        attrSet = 1;
    }
    dim3 grid(cdiv(N, 128), M / 128);
    k_mma2<<<grid, 256, SM2_BYTES>>>(M, N, K, Kpad / 32, A, bth, btl, Kpad,
                                     bias, C, aS, aH, stats, act);
}

extern "C" void kernel_launch(void* const* d_in, const int* in_sizes, int n_in,
                              void* d_out, int out_size) {
    const int*   x_atom  = (const int*)  d_in[0];
    const int*   src     = (const int*)  d_in[1];
    const int*   dst     = (const int*)  d_in[2];
    const int*   eattr   = (const int*)  d_in[3];
    const int*   batch   = (const int*)  d_in[4];
    const float* fp      = (const float*)d_in[5];
    const float* atom_emb= (const float*)d_in[6];
    const float* edge_emb= (const float*)d_in[7];
    const float* eps     = (const float*)d_in[8];
    const float* W1  = (const float*)d_in[9];
    const float* b1  = (const float*)d_in[10];
    const float* g1  = (const float*)d_in[11];
    const float* be1 = (const float*)d_in[12];
    const float* W2  = (const float*)d_in[13];
    const float* b2  = (const float*)d_in[14];
    const float* bng = (const float*)d_in[15];
    const float* bnb = (const float*)d_in[16];
    const float* vW1 = (const float*)d_in[17];
    const float* vb1 = (const float*)d_in[18];
    const float* vg1 = (const float*)d_in[19];
    const float* vbe1= (const float*)d_in[20];
    const float* vW2 = (const float*)d_in[21];
    const float* vb2 = (const float*)d_in[22];
    const float* vg2 = (const float*)d_in[23];
    const float* vbe2= (const float*)d_in[24];
    const float* pW1 = (const float*)d_in[25];
    const float* pb1 = (const float*)d_in[26];
    const float* pW2 = (const float*)d_in[27];
    const float* pb2 = (const float*)d_in[28];
    float* out = (float*)d_out;

    float *p_h, *p_hl, *p_acc, *p_y1, *p_y2, *p_vn, *p_vt, *p_u1, *p_u2,
          *p_hg, *p_t1, *p_stats, *p_scale, *p_shift;
    __nv_bfloat16 *p_bth, *p_btl;
    cudaGetSymbolAddress((void**)&p_h,    g_h);
    cudaGetSymbolAddress((void**)&p_hl,   g_hl);
    cudaGetSymbolAddress((void**)&p_acc,  g_acc);
    cudaGetSymbolAddress((void**)&p_y1,   g_y1);
    cudaGetSymbolAddress((void**)&p_y2,   g_y2);
    cudaGetSymbolAddress((void**)&p_vn,   g_vn);
    cudaGetSymbolAddress((void**)&p_vt,   g_vt);
    cudaGetSymbolAddress((void**)&p_u1,   g_u1);
    cudaGetSymbolAddress((void**)&p_u2,   g_u2);
    cudaGetSymbolAddress((void**)&p_hg,   g_hg);
    cudaGetSymbolAddress((void**)&p_t1,   g_t1);
    cudaGetSymbolAddress((void**)&p_stats,g_stats);
    cudaGetSymbolAddress((void**)&p_scale,g_scale);
    cudaGetSymbolAddress((void**)&p_shift,g_shift);
    cudaGetSymbolAddress((void**)&p_bth,  g_bth);
    cudaGetSymbolAddress((void**)&p_btl,  g_btl);

    const size_t ND  = (size_t)NN * DD;
    const size_t GD  = (size_t)GG * DD;
    const size_t ND4 = ND / 4;

    // pre-split all weights (transposed, bf16 hi/lo)
    for (int l = 0; l < LL; l++) {
        launch_split(W1 + (size_t)l * DD * DD2, DD, DD2, KP1,
                     p_bth + offW1(l), p_btl + offW1(l));
        launch_split(W2 + (size_t)l * DD2 * DD, DD2, DD, KP2,
                     p_bth + offW2(l), p_btl + offW2(l));
    }
    for (int l = 0; l < LL - 1; l++) {
        launch_split(vW1 + (size_t)l * DD * DD2, DD, DD2, KP1,
                     p_bth + offVW1(l), p_btl + offVW1(l));
        launch_split(vW2 + (size_t)l * DD2 * DD, DD2, DD, KP2,
                     p_bth + offVW2(l), p_btl + offVW2(l));
    }
    launch_split(pW1, HGC, H1, KPH1, p_bth + offPW1(), p_btl + offPW1());
    launch_split(pW2, H1, NT, KPH2, p_bth + offPW2(), p_btl + offPW2());

    k_zero<<<cdiv(GD, 256), 256>>>(p_vn, GD);
    k_embed<<<cdiv(ND4, 256), 256>>>(x_atom, atom_emb, p_h);

    for (int l = 0; l < LL; l++) {
        int doVt = (l < LL - 1);

        k_hl_acc<<<cdiv(ND4, 256), 256>>>(p_h, p_vn, batch, eps, l, p_hl, p_acc);

        k_edge<<<EE / 4, 300>>>(p_hl, edge_emb + (size_t)l * 5 * DD,
                                src, dst, eattr, p_acc);

        if (doVt)
            k_vt<<<GG, 128>>>(p_hl, batch, p_vn, p_vt);

        // GEMM1: acc[NN,300] @ W1[300,600] (+stats)
        k_zero<<<cdiv(2 * DD2, 256), 256>>>(p_stats, 2 * DD2);
        launch_mma2(NN, DD2, DD, KP1, p_acc, p_bth + offW1(l), p_btl + offW1(l),
                    b1 + (size_t)l * DD2, p_y1, nullptr, nullptr, p_stats, 0);
        k_bnfinal<<<cdiv(DD2, 256), 256>>>(p_stats, g1 + (size_t)l * DD2,
                                           be1 + (size_t)l * DD2, NN, DD2,
                                           p_scale, p_shift);

        // GEMM2: relu(bn(y1))[NN,600] @ W2[600,300] (+stats); BN fused on A-load
        k_zero<<<cdiv(2 * DD, 256), 256>>>(p_stats, 2 * DD);
        launch_mma2(NN, DD, DD2, KP2, p_y1, p_bth + offW2(l), p_btl + offW2(l),
                    b2 + (size_t)l * DD, p_y2, p_scale, p_shift, p_stats, 0);
        k_bnfinal<<<cdiv(DD, 256), 256>>>(p_stats, bng + (size_t)l * DD,
                                          bnb + (size_t)l * DD, NN, DD,
                                          p_scale, p_shift);
        k_bnapply<<<cdiv(ND4, 256), 256>>>(p_y2, p_h, ND4, DD / 4,
                                           p_scale, p_shift, doVt ? 1 : 0);

        if (doVt) {
            k_zero<<<cdiv(2 * DD2, 256), 256>>>(p_stats, 2 * DD2);
            launch_mma2(GG, DD2, DD, KP1, p_vt, p_bth + offVW1(l), p_btl + offVW1(l),
                        vb1 + (size_t)l * DD2, p_u1, nullptr, nullptr, p_stats, 0);
            k_bnfinal<<<cdiv(DD2, 256), 256>>>(p_stats, vg1 + (size_t)l * DD2,
                                               vbe1 + (size_t)l * DD2, GG, DD2,
                                               p_scale, p_shift);

            k_zero<<<cdiv(2 * DD, 256), 256>>>(p_stats, 2 * DD);
            launch_mma2(GG, DD, DD2, KP2, p_u1, p_bth + offVW2(l), p_btl + offVW2(l),
                        vb2 + (size_t)l * DD, p_u2, p_scale, p_shift, p_stats, 0);
            k_bnfinal<<<cdiv(DD, 256), 256>>>(p_stats, vg2 + (size_t)l * DD,
                                              vbe2 + (size_t)l * DD, GG, DD,
                                              p_scale, p_shift);
            k_bnapply<<<cdiv(GD / 4, 256), 256>>>(p_u2, p_vn, GD / 4, DD / 4,
                                                  p_scale, p_shift, 1);
        }
    }

    // head
    k_pool<<<GG, 256>>>(p_h, batch, fp, p_hg);
    launch_mma2(GG, H1, HGC, KPH1, p_hg, p_bth + offPW1(), p_btl + offPW1(),
                pb1, p_t1, nullptr, nullptr, nullptr, 2);
    launch_mma2(GG, NT, H1, KPH2, p_t1, p_bth + offPW2(), p_btl + offPW2(),
                pb2, out, nullptr, nullptr, nullptr, 0);
}

// round 8
// speedup vs baseline: 1.2837x; 1.2837x over previous
#include <cuda_runtime.h>
#include <cuda_bf16.h>
#include <cstdint>
#include <math.h>

// Problem constants
#define NN 262144
#define EE 524288
#define GG 8192
#define DD 300
#define DD2 600
#define LL 5
#define HGC 2348
#define H1 1200
#define NT 128

// ---------------- scratch (device globals; total ~1.81 GB) ----------------
__device__ float g_h  [(size_t)NN * DD];    // 314.6 MB
__device__ float g_acc[(size_t)NN * DD];    // 314.6 MB (GIN accum; reused as y2/u2-node out)
__device__ float g_vn [(size_t)GG * DD];
__device__ float g_vt [(size_t)GG * DD];
__device__ float g_u2 [(size_t)GG * DD];
__device__ float g_hg [(size_t)GG * HGC];   // 77 MB
__device__ float g_t1 [(size_t)GG * H1];    // 39.3 MB
__device__ float g_stats[2 * DD2];
__device__ float g_scale[DD2];
__device__ float g_shift[DD2];

// pre-split transposed weights: [N, Kpad] bf16 hi / lo (12.9 MB each)
#define BT_TOTAL 6453248
__device__ __nv_bfloat16 g_bth[BT_TOTAL];
__device__ __nv_bfloat16 g_btl[BT_TOTAL];

// split operand planes
#define A320_ELEMS ((size_t)NN * 320)   // 167.8 MB per plane
#define Y640_ELEMS ((size_t)NN * 640)   // 335.5 MB per plane
__device__ __nv_bfloat16 g_a3h[A320_ELEMS];
__device__ __nv_bfloat16 g_a3l[A320_ELEMS];
__device__ __nv_bfloat16 g_y6h[Y640_ELEMS];
__device__ __nv_bfloat16 g_y6l[Y640_ELEMS];

// ---------------- helpers ----------------
__device__ __forceinline__ uint32_t packbf2(float a, float b) {
    __nv_bfloat162 t = __floats2bfloat162_rn(a, b);
    return *reinterpret_cast<uint32_t*>(&t);
}
__device__ __forceinline__ float bf_hi(float x) {
    return __bfloat162float(__float2bfloat16_rn(x));
}
__device__ __forceinline__ float gelu_tanh(float x) {
    const float k0 = 0.7978845608028654f;
    const float k1 = 0.044715f;
    float x3 = x * x * x;
    return 0.5f * x * (1.f + tanhf(k0 * (x + k1 * x3)));
}

__device__ __forceinline__ void mma_bf16(float* d, const uint32_t* a, const uint32_t* b) {
    asm volatile(
        "mma.sync.aligned.m16n8k16.row.col.f32.bf16.bf16.f32 "
        "{%0,%1,%2,%3}, {%4,%5,%6,%7}, {%8,%9}, {%0,%1,%2,%3};\n"
        : "+f"(d[0]), "+f"(d[1]), "+f"(d[2]), "+f"(d[3])
        : "r"(a[0]), "r"(a[1]), "r"(a[2]), "r"(a[3]),
          "r"(b[0]), "r"(b[1]));
}

// ---------------- utility kernels ----------------
__global__ void k_zero(float* p, size_t n) {
    size_t i = (size_t)blockIdx.x * blockDim.x + threadIdx.x;
    if (i < n) p[i] = 0.f;
}

__global__ void k_embed(const int* __restrict__ x_atom,
                        const float* __restrict__ atom_emb,
                        float* __restrict__ h) {
    size_t idx4 = (size_t)blockIdx.x * blockDim.x + threadIdx.x;
    size_t tot4 = (size_t)NN * DD / 4;
    if (idx4 >= tot4) return;
    int i  = (int)(idx4 / (DD / 4));
    int c4 = (int)(idx4 - (size_t)i * (DD / 4));
    const float4* srcv = (const float4*)(atom_emb + (size_t)x_atom[i] * DD);
    ((float4*)h)[idx4] = srcv[c4];
}

// acc = (1+eps_l) * (h + vn[batch])
__global__ void k_acc(const float* __restrict__ h,
                      const float* __restrict__ vn,
                      const int* __restrict__ batch,
                      const float* __restrict__ eps, int l,
                      float* __restrict__ acc) {
    size_t idx4 = (size_t)blockIdx.x * blockDim.x + threadIdx.x;
    size_t tot4 = (size_t)NN * DD / 4;
    if (idx4 >= tot4) return;
    int i  = (int)(idx4 / (DD / 4));
    int c4 = (int)(idx4 - (size_t)i * (DD / 4));
    int b  = batch[i];
    float e = 1.f + eps[l];
    float4 hv = ((const float4*)h)[idx4];
    float4 vv = ((const float4*)(vn + (size_t)b * DD))[c4];
    float4 a;
    a.x = e * (hv.x + vv.x); a.y = e * (hv.y + vv.y);
    a.z = e * (hv.z + vv.z); a.w = e * (hv.w + vv.w);
    ((float4*)acc)[idx4] = a;
}

// edge scatter: acc[dst] += relu(h[src] + vn[batch[src]] + eemb[attr])
__global__ void k_edge(const float* __restrict__ h,
                       const float* __restrict__ vn,
                       const int* __restrict__ batch,
                       const float* __restrict__ eemb,
                       const int* __restrict__ src,
                       const int* __restrict__ dst,
                       const int* __restrict__ eattr,
                       float* __restrict__ acc) {
    int sub = threadIdx.x / 75;
    int c4  = threadIdx.x % 75;
    int e = blockIdx.x * 4 + sub;
    int s = src[e], d = dst[e], a = eattr[e];
    int b = batch[s];
    float4 hv = *(const float4*)(h    + (size_t)s * DD + c4 * 4);
    float4 vv = *(const float4*)(vn   + (size_t)b * DD + c4 * 4);
    float4 ev = *(const float4*)(eemb + (size_t)a * DD + c4 * 4);
    float* out = acc + (size_t)d * DD + c4 * 4;
    float m;
    m = hv.x + vv.x + ev.x; if (m > 0.f) atomicAdd(out + 0, m);
    m = hv.y + vv.y + ev.y; if (m > 0.f) atomicAdd(out + 1, m);
    m = hv.z + vv.z + ev.z; if (m > 0.f) atomicAdd(out + 2, m);
    m = hv.w + vv.w + ev.w; if (m > 0.f) atomicAdd(out + 3, m);
}

__device__ __forceinline__ int lbound(const int* __restrict__ arr, int n, int val) {
    int lo = 0, hi = n;
    while (lo < hi) { int mid = (lo + hi) >> 1; if (arr[mid] < val) lo = mid + 1; else hi = mid; }
    return lo;
}

// vt[g] = (1+cnt_g)*vn[g] + sum_{i in g} h[i]
__global__ void k_vt(const float* __restrict__ h, const int* __restrict__ batch,
                     const float* __restrict__ vn, float* __restrict__ vt) {
    int g = blockIdx.x;
    __shared__ int ss, se;
    if (threadIdx.x == 0) { ss = lbound(batch, NN, g); se = lbound(batch, NN, g + 1); }
    __syncthreads();
    int s0 = ss, s1 = se;
    float f = 1.f + (float)(s1 - s0);
    for (int c = threadIdx.x; c < DD; c += blockDim.x) {
        float s = f * vn[(size_t)g * DD + c];
        for (int r = s0; r < s1; r++) s += h[(size_t)r * DD + c];
        vt[(size_t)g * DD + c] = s;
    }
}

__global__ void k_pool(const float* __restrict__ h, const int* __restrict__ batch,
                       const float* __restrict__ fp, float* __restrict__ hg) {
    int g = blockIdx.x;
    __shared__ int ss, se;
    if (threadIdx.x == 0) { ss = lbound(batch, NN, g); se = lbound(batch, NN, g + 1); }
    __syncthreads();
    int s0 = ss, s1 = se;
    for (int c = threadIdx.x; c < HGC; c += blockDim.x) {
        float v;
        if (c < DD) {
            v = 0.f;
            for (int r = s0; r < s1; r++) v += h[(size_t)r * DD + c];
        } else {
            v = fp[(size_t)g * 2048 + (c - DD)];
        }
        hg[(size_t)g * HGC + c] = v;
    }
}

__global__ void k_bnfinal(const float* __restrict__ stats,
                          const float* __restrict__ gamma,
                          const float* __restrict__ beta,
                          int M, int C,
                          float* __restrict__ scale, float* __restrict__ shift) {
    int c = blockIdx.x * blockDim.x + threadIdx.x;
    if (c >= C) return;
    float inv = 1.f / (float)M;
    float mean = stats[c] * inv;
    float var  = stats[C + c] * inv - mean * mean;
    float s = gamma[c] * rsqrtf(var + 1e-5f);
    scale[c] = s;
    shift[c] = beta[c] - mean * s;
}

__global__ void k_bnapply(const float* __restrict__ X, float* __restrict__ Y,
                          size_t total4, int C4,
                          const float* __restrict__ scale,
                          const float* __restrict__ shift, int relu) {
    size_t idx4 = (size_t)blockIdx.x * blockDim.x + threadIdx.x;
    if (idx4 >= total4) return;
    int c4 = (int)(idx4 % C4) * 4;
    float4 x = ((const float4*)X)[idx4];
    float4 o;
    o.x = x.x * scale[c4 + 0] + shift[c4 + 0];
    o.y = x.y * scale[c4 + 1] + shift[c4 + 1];
    o.z = x.z * scale[c4 + 2] + shift[c4 + 2];
    o.w = x.w * scale[c4 + 3] + shift[c4 + 3];
    if (relu) {
        o.x = fmaxf(o.x, 0.f); o.y = fmaxf(o.y, 0.f);
        o.z = fmaxf(o.z, 0.f); o.w = fmaxf(o.w, 0.f);
    }
    ((float4*)Y)[idx4] = o;
}

// Split activation X[M,C] fp32 -> XH/XL [M,Cpad] bf16 (zero-padded)
__global__ void k_split_act(const float* __restrict__ X, int C, int Cpad, int M,
                            __nv_bfloat16* __restrict__ XH,
                            __nv_bfloat16* __restrict__ XL) {
    size_t idx = (size_t)blockIdx.x * blockDim.x + threadIdx.x;
    int cp4 = Cpad / 4;
    size_t tot = (size_t)M * cp4;
    if (idx >= tot) return;
    int r  = (int)(idx / cp4);
    int c  = (int)(idx - (size_t)r * cp4) * 4;
    float4 v = make_float4(0.f, 0.f, 0.f, 0.f);
    if (c < C) v = *(const float4*)(X + (size_t)r * C + c);
    float hx = bf_hi(v.x), hy = bf_hi(v.y), hz = bf_hi(v.z), hw = bf_hi(v.w);
    uint2 hv = make_uint2(packbf2(hx, hy), packbf2(hz, hw));
    uint2 lv = make_uint2(packbf2(v.x - hx, v.y - hy), packbf2(v.z - hz, v.w - hw));
    *(uint2*)(XH + (size_t)r * Cpad + c) = hv;
    *(uint2*)(XL + (size_t)r * Cpad + c) = lv;
}

// In-place BN(+relu) on split planes: v = hi+lo; v' = relu(v*scale+shift); re-split.
// Pads (c >= C) are set to zero.
__global__ void k_resplit(__nv_bfloat16* __restrict__ XH,
                          __nv_bfloat16* __restrict__ XL,
                          int C, int Cpad, int M,
                          const float* __restrict__ scale,
                          const float* __restrict__ shift) {
    size_t idx = (size_t)blockIdx.x * blockDim.x + threadIdx.x;
    int cp4 = Cpad / 4;
    size_t tot = (size_t)M * cp4;
    if (idx >= tot) return;
    int r  = (int)(idx / cp4);
    int c  = (int)(idx - (size_t)r * cp4) * 4;
    size_t o = (size_t)r * Cpad + c;
    float4 v = make_float4(0.f, 0.f, 0.f, 0.f);
    if (c < C) {
        uint2 hv = *(const uint2*)(XH + o);
        uint2 lv = *(const uint2*)(XL + o);
        __nv_bfloat162 h01 = *reinterpret_cast<__nv_bfloat162*>(&hv.x);
        __nv_bfloat162 h23 = *reinterpret_cast<__nv_bfloat162*>(&hv.y);
        __nv_bfloat162 l01 = *reinterpret_cast<__nv_bfloat162*>(&lv.x);
        __nv_bfloat162 l23 = *reinterpret_cast<__nv_bfloat162*>(&lv.y);
        v.x = __bfloat162float(h01.x) + __bfloat162float(l01.x);
        v.y = __bfloat162float(h01.y) + __bfloat162float(l01.y);
        v.z = __bfloat162float(h23.x) + __bfloat162float(l23.x);
        v.w = __bfloat162float(h23.y) + __bfloat162float(l23.y);
        v.x = fmaxf(v.x * scale[c + 0] + shift[c + 0], 0.f);
        v.y = fmaxf(v.y * scale[c + 1] + shift[c + 1], 0.f);
        v.z = fmaxf(v.z * scale[c + 2] + shift[c + 2], 0.f);
        v.w = fmaxf(v.w * scale[c + 3] + shift[c + 3], 0.f);
    }
    float hx = bf_hi(v.x), hy = bf_hi(v.y), hz = bf_hi(v.z), hw = bf_hi(v.w);
    *(uint2*)(XH + o) = make_uint2(packbf2(hx, hy), packbf2(hz, hw));
    *(uint2*)(XL + o) = make_uint2(packbf2(v.x - hx, v.y - hy), packbf2(v.z - hz, v.w - hw));
}

// Transpose + split weights: W[K,N] fp32 -> BTH/BTL[n*Kpad + k] bf16 (zero-padded)
__global__ void k_split_w(const float* __restrict__ W, int K, int N, int Kpad,
                          __nv_bfloat16* __restrict__ bth,
                          __nv_bfloat16* __restrict__ btl) {
    __shared__ float tile[32][33];
    int nb = blockIdx.x * 32, kb = blockIdx.y * 32;
    int tx = threadIdx.x, ty = threadIdx.y;
    for (int i = ty; i < 32; i += 8) {
        int k = kb + i, n = nb + tx;
        tile[i][tx] = (k < K && n < N) ? W[(size_t)k * N + n] : 0.f;
    }
    __syncthreads();
    for (int i = ty; i < 32; i += 8) {
        int n = nb + i, k = kb + tx;
        if (n < N && k < Kpad) {
            float v = tile[tx][i];
            float h = bf_hi(v);
            bth[(size_t)n * Kpad + k] = __float2bfloat16_rn(h);
            btl[(size_t)n * Kpad + k] = __float2bfloat16_rn(v - h);
        }
    }
}

// ---------------- bf16x3 mma.sync GEMM, pre-split operands ----------------
// D[M,N] = A @ BT^T + bias ; A = AH+AL [M,Kpad], BT = BH+BL [N,Kpad].
// Output: either fp32 C (with act) or split planes CH/CL [M,Npad] (pre-activation).
// Optional column sum/sumsq of pre-activation D into stats[0:N), stats[N:2N).

#define SMP 136

__global__ __launch_bounds__(256, 2)
void k_mma3(int M, int N, int KT,
            const __nv_bfloat16* __restrict__ AH,
            const __nv_bfloat16* __restrict__ AL,
            const __nv_bfloat16* __restrict__ BH,
            const __nv_bfloat16* __restrict__ BL, int Kpad,
            const float* __restrict__ bias,
            float* __restrict__ C,
            __nv_bfloat16* __restrict__ CH,
            __nv_bfloat16* __restrict__ CL, int Npad,
            float* stats, int act) {
    __shared__ uint32_t AsH[2][8][SMP];
    __shared__ uint32_t AsL[2][8][SMP];
    __shared__ uint32_t BsH[2][8][SMP];
    __shared__ uint32_t BsL[2][8][SMP];

    const int tid  = threadIdx.x;
    const int lane = tid & 31;
    const int warp = tid >> 5;
    const int warpM = warp >> 2;        // 0..1
    const int warpN = warp & 3;         // 0..3
    const int gID = lane >> 2;          // 0..7
    const int tg  = lane & 3;           // 0..3
    const int rowBase = blockIdx.y * 128;
    const int colBase = blockIdx.x * 128;

    const int lr = tid & 127;
    const int lq = tid >> 7;

    float acc[4][4][4];
    #pragma unroll
    for (int i = 0; i < 4; i++)
        #pragma unroll
        for (int j = 0; j < 4; j++)
            #pragma unroll
            for (int r = 0; r < 4; r++) acc[i][j][r] = 0.f;

    uint4 vAH, vAL, vBH, vBL;
    const bool bValid = (colBase + lr) < N;

    auto loadTile = [&](int t) {
        int k0 = t * 16 + lq * 8;
        size_t ao = (size_t)(rowBase + lr) * Kpad + k0;
        vAH = *(const uint4*)(AH + ao);
        vAL = *(const uint4*)(AL + ao);
        vBH = make_uint4(0, 0, 0, 0);
        vBL = make_uint4(0, 0, 0, 0);
        if (bValid) {
            size_t bo = (size_t)(colBase + lr) * Kpad + k0;
            vBH = *(const uint4*)(BH + bo);
            vBL = *(const uint4*)(BL + bo);
        }
    };
    auto storeTile = [&](int buf) {
        AsH[buf][lq * 4 + 0][lr] = vAH.x;
        AsH[buf][lq * 4 + 1][lr] = vAH.y;
        AsH[buf][lq * 4 + 2][lr] = vAH.z;
        AsH[buf][lq * 4 + 3][lr] = vAH.w;
        AsL[buf][lq * 4 + 0][lr] = vAL.x;
        AsL[buf][lq * 4 + 1][lr] = vAL.y;
        AsL[buf][lq * 4 + 2][lr] = vAL.z;
        AsL[buf][lq * 4 + 3][lr] = vAL.w;
        BsH[buf][lq * 4 + 0][lr] = vBH.x;
        BsH[buf][lq * 4 + 1][lr] = vBH.y;
        BsH[buf][lq * 4 + 2][lr] = vBH.z;
        BsH[buf][lq * 4 + 3][lr] = vBH.w;
        BsL[buf][lq * 4 + 0][lr] = vBL.x;
        BsL[buf][lq * 4 + 1][lr] = vBL.y;
        BsL[buf][lq * 4 + 2][lr] = vBL.z;
        BsL[buf][lq * 4 + 3][lr] = vBL.w;
    };

    loadTile(0);
    storeTile(0);
    __syncthreads();

    for (int t = 0; t < KT; t++) {
        int buf = t & 1;
        if (t + 1 < KT) loadTile(t + 1);

        uint32_t bh[4][2], bl[4][2];
        #pragma unroll
        for (int nt = 0; nt < 4; nt++) {
            int c = warpN * 32 + nt * 8 + gID;
            bh[nt][0] = BsH[buf][tg    ][c];
            bh[nt][1] = BsH[buf][tg + 4][c];
            bl[nt][0] = BsL[buf][tg    ][c];
            bl[nt][1] = BsL[buf][tg + 4][c];
        }
        #pragma unroll
        for (int mt = 0; mt < 4; mt++) {
            int r0 = warpM * 64 + mt * 16 + gID;
            uint32_t ah[4], al[4];
            ah[0] = AsH[buf][tg    ][r0];
            ah[1] = AsH[buf][tg    ][r0 + 8];
            ah[2] = AsH[buf][tg + 4][r0];
            ah[3] = AsH[buf][tg + 4][r0 + 8];
            al[0] = AsL[buf][tg    ][r0];
            al[1] = AsL[buf][tg    ][r0 + 8];
            al[2] = AsL[buf][tg + 4][r0];
            al[3] = AsL[buf][tg + 4][r0 + 8];
            #pragma unroll
            for (int nt = 0; nt < 4; nt++) {
                mma_bf16(acc[mt][nt], ah, bh[nt]);
                mma_bf16(acc[mt][nt], ah, bl[nt]);
                mma_bf16(acc[mt][nt], al, bh[nt]);
            }
        }

        if (t + 1 < KT) storeTile(buf ^ 1);
        __syncthreads();
    }

    // ---- epilogue ----
    const bool doStats = (stats != nullptr);
    const bool outSplit = (CH != nullptr);
    float* sstat = reinterpret_cast<float*>(&AsH[0][0][0]);  // 256 floats scratch
    if (doStats) {
        if (tid < 256) sstat[tid] = 0.f;
        __syncthreads();
    }

    #pragma unroll
    for (int nt = 0; nt < 4; nt++) {
        #pragma unroll
        for (int p = 0; p < 2; p++) {
            int lc = warpN * 32 + nt * 8 + 2 * tg + p;
            int col = colBase + lc;
            bool cv = col < N;
            float bs = cv ? __ldg(bias + col) : 0.f;
            float s = 0.f, s2 = 0.f;
            #pragma unroll
            for (int mt = 0; mt < 4; mt++) {
                int row = rowBase + warpM * 64 + mt * 16 + gID;
                #pragma unroll
                for (int hh = 0; hh < 2; hh++) {
                    float v = acc[mt][nt][p + 2 * hh] + bs;
                    s += v; s2 += v * v;
                    if (cv) {
                        size_t ro = (size_t)(row + 8 * hh);
                        if (outSplit) {
                            float hf = bf_hi(v);
                            CH[ro * Npad + col] = __float2bfloat16_rn(hf);
                            CL[ro * Npad + col] = __float2bfloat16_rn(v - hf);
                        } else {
                            float o = v;
                            if (act == 1) o = fmaxf(o, 0.f);
                            else if (act == 2) o = gelu_tanh(o);
                            C[ro * N + col] = o;
                        }
                    }
                }
            }
            if (doStats && cv) {
                atomicAdd(&sstat[lc], s);
                atomicAdd(&sstat[128 + lc], s2);
            }
        }
    }
    if (doStats) {
        __syncthreads();
        if (tid < 128) {
            int col = colBase + tid;
            if (col < N) {
                atomicAdd(&stats[col], sstat[tid]);
                atomicAdd(&stats[N + col], sstat[128 + tid]);
            }
        }
    }
}

// ---------------- host orchestration ----------------
static inline int cdiv(long long a, long long b) { return (int)((a + b - 1) / b); }

// BT offsets (elements)
#define KP1 320
#define KP2 640
#define KPH1 2368
#define KPH2 1216
static inline size_t offW1(int l)  { return (size_t)l * 192000; }
static inline size_t offW2(int l)  { return 960000 + (size_t)l * 192000; }
static inline size_t offVW1(int l) { return 1920000 + (size_t)l * 192000; }
static inline size_t offVW2(int l) { return 2688000 + (size_t)l * 192000; }
static inline size_t offPW1()      { return 3456000; }
static inline size_t offPW2()      { return 6297600; }

static void launch_split_w(const float* W, int K, int N, int Kpad,
                           __nv_bfloat16* bth, __nv_bfloat16* btl) {
    dim3 grid(cdiv(N, 32), cdiv(Kpad, 32));
    k_split_w<<<grid, dim3(32, 8)>>>(W, K, N, Kpad, bth, btl);
}

static void launch_split_act(const float* X, int C, int Cpad, int M,
                             __nv_bfloat16* XH, __nv_bfloat16* XL) {
    size_t tot = (size_t)M * (Cpad / 4);
    k_split_act<<<cdiv(tot, 256), 256>>>(X, C, Cpad, M, XH, XL);
}

static void launch_resplit(__nv_bfloat16* XH, __nv_bfloat16* XL, int C, int Cpad,
                           int M, const float* scale, const float* shift) {
    size_t tot = (size_t)M * (Cpad / 4);
    k_resplit<<<cdiv(tot, 256), 256>>>(XH, XL, C, Cpad, M, scale, shift);
}

static void launch_mma3(int M, int N, int Kpad,
                        const __nv_bfloat16* aH, const __nv_bfloat16* aL,
                        const __nv_bfloat16* bH, const __nv_bfloat16* bL,
                        const float* bias, float* C,
                        __nv_bfloat16* CH, __nv_bfloat16* CL, int Npad,
                        float* stats, int act) {
    dim3 grid(cdiv(N, 128), M / 128);
    k_mma3<<<grid, 256>>>(M, N, Kpad / 16, aH, aL, bH, bL, Kpad,
                          bias, C, CH, CL, Npad, stats, act);
}

extern "C" void kernel_launch(void* const* d_in, const int* in_sizes, int n_in,
                              void* d_out, int out_size) {
    const int*   x_atom  = (const int*)  d_in[0];
    const int*   src     = (const int*)  d_in[1];
    const int*   dst     = (const int*)  d_in[2];
    const int*   eattr   = (const int*)  d_in[3];
    const int*   batch   = (const int*)  d_in[4];
    const float* fp      = (const float*)d_in[5];
    const float* atom_emb= (const float*)d_in[6];
    const float* edge_emb= (const float*)d_in[7];
    const float* eps     = (const float*)d_in[8];
    const float* W1  = (const float*)d_in[9];
    const float* b1  = (const float*)d_in[10];
    const float* g1  = (const float*)d_in[11];
    const float* be1 = (const float*)d_in[12];
    const float* W2  = (const float*)d_in[13];
    const float* b2  = (const float*)d_in[14];
    const float* bng = (const float*)d_in[15];
    const float* bnb = (const float*)d_in[16];
    const float* vW1 = (const float*)d_in[17];
    const float* vb1 = (const float*)d_in[18];
    const float* vg1 = (const float*)d_in[19];
    const float* vbe1= (const float*)d_in[20];
    const float* vW2 = (const float*)d_in[21];
    const float* vb2 = (const float*)d_in[22];
    const float* vg2 = (const float*)d_in[23];
    const float* vbe2= (const float*)d_in[24];
    const float* pW1 = (const float*)d_in[25];
    const float* pb1 = (const float*)d_in[26];
    const float* pW2 = (const float*)d_in[27];
    const float* pb2 = (const float*)d_in[28];
    float* out = (float*)d_out;

    float *p_h, *p_acc, *p_vn, *p_vt, *p_u2, *p_hg, *p_t1,
          *p_stats, *p_scale, *p_shift;
    __nv_bfloat16 *p_bth, *p_btl, *p_a3h, *p_a3l, *p_y6h, *p_y6l;
    cudaGetSymbolAddress((void**)&p_h,    g_h);
    cudaGetSymbolAddress((void**)&p_acc,  g_acc);
    cudaGetSymbolAddress((void**)&p_vn,   g_vn);
    cudaGetSymbolAddress((void**)&p_vt,   g_vt);
    cudaGetSymbolAddress((void**)&p_u2,   g_u2);
    cudaGetSymbolAddress((void**)&p_hg,   g_hg);
    cudaGetSymbolAddress((void**)&p_t1,   g_t1);
    cudaGetSymbolAddress((void**)&p_stats,g_stats);
    cudaGetSymbolAddress((void**)&p_scale,g_scale);
    cudaGetSymbolAddress((void**)&p_shift,g_shift);
    cudaGetSymbolAddress((void**)&p_bth,  g_bth);
    cudaGetSymbolAddress((void**)&p_btl,  g_btl);
    cudaGetSymbolAddress((void**)&p_a3h,  g_a3h);
    cudaGetSymbolAddress((void**)&p_a3l,  g_a3l);
    cudaGetSymbolAddress((void**)&p_y6h,  g_y6h);
    cudaGetSymbolAddress((void**)&p_y6l,  g_y6l);

    const size_t ND  = (size_t)NN * DD;
    const size_t GD  = (size_t)GG * DD;
    const size_t ND4 = ND / 4;

    // pre-split all weights (transposed, bf16 hi/lo)
    for (int l = 0; l < LL; l++) {
        launch_split_w(W1 + (size_t)l * DD * DD2, DD, DD2, KP1,
                       p_bth + offW1(l), p_btl + offW1(l));
        launch_split_w(W2 + (size_t)l * DD2 * DD, DD2, DD, KP2,
                       p_bth + offW2(l), p_btl + offW2(l));
    }
    for (int l = 0; l < LL - 1; l++) {
        launch_split_w(vW1 + (size_t)l * DD * DD2, DD, DD2, KP1,
                       p_bth + offVW1(l), p_btl + offVW1(l));
        launch_split_w(vW2 + (size_t)l * DD2 * DD, DD2, DD, KP2,
                       p_bth + offVW2(l), p_btl + offVW2(l));
    }
    launch_split_w(pW1, HGC, H1, KPH1, p_bth + offPW1(), p_btl + offPW1());
    launch_split_w(pW2, H1, NT, KPH2, p_bth + offPW2(), p_btl + offPW2());

    k_zero<<<cdiv(GD, 256), 256>>>(p_vn, GD);
    k_embed<<<cdiv(ND4, 256), 256>>>(x_atom, atom_emb, p_h);

    for (int l = 0; l < LL; l++) {
        int doVt = (l < LL - 1);

        k_acc<<<cdiv(ND4, 256), 256>>>(p_h, p_vn, batch, eps, l, p_acc);

        k_edge<<<EE / 4, 300>>>(p_h, p_vn, batch, edge_emb + (size_t)l * 5 * DD,
                                src, dst, eattr, p_acc);

        if (doVt)
            k_vt<<<GG, 128>>>(p_h, batch, p_vn, p_vt);

        // GEMM1: split(acc) @ W1 -> Y640 split (+stats)
        launch_split_act(p_acc, DD, KP1, NN, p_a3h, p_a3l);
        k_zero<<<cdiv(2 * DD2, 256), 256>>>(p_stats, 2 * DD2);
        launch_mma3(NN, DD2, KP1, p_a3h, p_a3l, p_bth + offW1(l), p_btl + offW1(l),
                    b1 + (size_t)l * DD2, nullptr, p_y6h, p_y6l, KP2, p_stats, 0);
        k_bnfinal<<<cdiv(DD2, 256), 256>>>(p_stats, g1 + (size_t)l * DD2,
                                           be1 + (size_t)l * DD2, NN, DD2,
                                           p_scale, p_shift);
        // BN+relu in-place on Y640 planes
        launch_resplit(p_y6h, p_y6l, DD2, KP2, NN, p_scale, p_shift);

        // GEMM2: Y640 @ W2 -> acc fp32 (+stats)
        k_zero<<<cdiv(2 * DD, 256), 256>>>(p_stats, 2 * DD);
        launch_mma3(NN, DD, KP2, p_y6h, p_y6l, p_bth + offW2(l), p_btl + offW2(l),
                    b2 + (size_t)l * DD, p_acc, nullptr, nullptr, 0, p_stats, 0);
        k_bnfinal<<<cdiv(DD, 256), 256>>>(p_stats, bng + (size_t)l * DD,
                                          bnb + (size_t)l * DD, NN, DD,
                                          p_scale, p_shift);
        k_bnapply<<<cdiv(ND4, 256), 256>>>(p_acc, p_h, ND4, DD / 4,
                                           p_scale, p_shift, doVt ? 1 : 0);

        if (doVt) {
            launch_split_act(p_vt, DD, KP1, GG, p_a3h, p_a3l);
            k_zero<<<cdiv(2 * DD2, 256), 256>>>(p_stats, 2 * DD2);
            launch_mma3(GG, DD2, KP1, p_a3h, p_a3l,
                        p_bth + offVW1(l), p_btl + offVW1(l),
                        vb1 + (size_t)l * DD2, nullptr, p_y6h, p_y6l, KP2, p_stats, 0);
            k_bnfinal<<<cdiv(DD2, 256), 256>>>(p_stats, vg1 + (size_t)l * DD2,
                                               vbe1 + (size_t)l * DD2, GG, DD2,
                                               p_scale, p_shift);
            launch_resplit(p_y6h, p_y6l, DD2, KP2, GG, p_scale, p_shift);

            k_zero<<<cdiv(2 * DD, 256), 256>>>(p_stats, 2 * DD);
            launch_mma3(GG, DD, KP2, p_y6h, p_y6l,
                        p_bth + offVW2(l), p_btl + offVW2(l),
                        vb2 + (size_t)l * DD, p_u2, nullptr, nullptr, 0, p_stats, 0);
            k_bnfinal<<<cdiv(DD, 256), 256>>>(p_stats, vg2 + (size_t)l * DD,
                                              vbe2 + (size_t)l * DD, GG, DD,
                                              p_scale, p_shift);
            k_bnapply<<<cdiv(GD / 4, 256), 256>>>(p_u2, p_vn, GD / 4, DD / 4,
                                                  p_scale, p_shift, 1);
        }
    }

    // head
    k_pool<<<GG, 256>>>(p_h, batch, fp, p_hg);
    launch_split_act(p_hg, HGC, KPH1, GG, p_a3h, p_a3l);
    launch_mma3(GG, H1, KPH1, p_a3h, p_a3l, p_bth + offPW1(), p_btl + offPW1(),
                pb1, p_t1, nullptr, nullptr, 0, nullptr, 2);
    launch_split_act(p_t1, H1, KPH2, GG, p_y6h, p_y6l);
    launch_mma3(GG, NT, KPH2, p_y6h, p_y6l, p_bth + offPW2(), p_btl + offPW2(),
                pb2, out, nullptr, nullptr, 0, nullptr, 0);
}

// round 10
// speedup vs baseline: 1.6547x; 1.2891x over previous
#include <cuda_runtime.h>
#include <cuda_bf16.h>
#include <cstdint>
#include <math.h>

// Problem constants
#define NN 262144
#define EE 524288
#define GG 8192
#define DD 300
#define DD2 600
#define LL 5
#define HGC 2348
#define H1 1200
#define NT 128

// ---------------- scratch (device globals) ----------------
__device__ float g_h  [(size_t)NN * DD];
__device__ float g_hl [(size_t)NN * DD];
__device__ float g_acc[(size_t)NN * DD];
__device__ float g_y1 [(size_t)NN * DD2];
__device__ float g_y2 [(size_t)NN * DD];
__device__ float g_vn [(size_t)GG * DD];
__device__ float g_vt [(size_t)GG * DD];
__device__ float g_u1 [(size_t)GG * DD2];
__device__ float g_u2 [(size_t)GG * DD];
__device__ float g_hg [(size_t)GG * HGC];
__device__ float g_t1 [(size_t)GG * H1];
__device__ float g_stats[2 * DD2];
__device__ float g_scale[DD2];
__device__ float g_shift[DD2];

// ---------------- utility kernels ----------------
__global__ void k_zero(float* p, size_t n) {
    size_t i = (size_t)blockIdx.x * blockDim.x + threadIdx.x;
    if (i < n) p[i] = 0.f;
}

__global__ void k_embed(const int* __restrict__ x_atom,
                        const float* __restrict__ atom_emb,
                        float* __restrict__ h) {
    size_t idx4 = (size_t)blockIdx.x * blockDim.x + threadIdx.x;
    size_t tot4 = (size_t)NN * DD / 4;
    if (idx4 >= tot4) return;
    int i  = (int)(idx4 / (DD / 4));
    int c4 = (int)(idx4 - (size_t)i * (DD / 4));
    const float4* srcv = (const float4*)(atom_emb + (size_t)x_atom[i] * DD);
    ((float4*)h)[idx4] = srcv[c4];
}

// hl = h + vn[batch]; acc = (1+eps_l)*hl
__global__ void k_hl_acc(const float* __restrict__ h,
                         const float* __restrict__ vn,
                         const int* __restrict__ batch,
                         const float* __restrict__ eps, int l,
                         float* __restrict__ hl,
                         float* __restrict__ acc) {
    size_t idx4 = (size_t)blockIdx.x * blockDim.x + threadIdx.x;
    size_t tot4 = (size_t)NN * DD / 4;
    if (idx4 >= tot4) return;
    int i  = (int)(idx4 / (DD / 4));
    int c4 = (int)(idx4 - (size_t)i * (DD / 4));
    int b  = batch[i];
    float e = 1.f + eps[l];
    float4 hv = ((const float4*)h)[idx4];
    float4 vv = ((const float4*)(vn + (size_t)b * DD))[c4];
    float4 o, a;
    o.x = hv.x + vv.x; o.y = hv.y + vv.y; o.z = hv.z + vv.z; o.w = hv.w + vv.w;
    a.x = e * o.x; a.y = e * o.y; a.z = e * o.z; a.w = e * o.w;
    ((float4*)hl)[idx4] = o;
    ((float4*)acc)[idx4] = a;
}

// edge scatter: 4 edges / 300-thread block
__global__ void k_edge(const float* __restrict__ hl,
                       const float* __restrict__ eemb,
                       const int* __restrict__ src,
                       const int* __restrict__ dst,
                       const int* __restrict__ eattr,
                       float* __restrict__ acc) {
    int sub = threadIdx.x / 75;
    int c4  = threadIdx.x % 75;
    int e = blockIdx.x * 4 + sub;
    int s = src[e], d = dst[e], a = eattr[e];
    float4 hv = *(const float4*)(hl   + (size_t)s * DD + c4 * 4);
    float4 ev = *(const float4*)(eemb + (size_t)a * DD + c4 * 4);
    float* out = acc + (size_t)d * DD + c4 * 4;
    float m;
    m = hv.x + ev.x; if (m > 0.f) atomicAdd(out + 0, m);
    m = hv.y + ev.y; if (m > 0.f) atomicAdd(out + 1, m);
    m = hv.z + ev.z; if (m > 0.f) atomicAdd(out + 2, m);
    m = hv.w + ev.w; if (m > 0.f) atomicAdd(out + 3, m);
}

__device__ __forceinline__ int lbound(const int* __restrict__ arr, int n, int val) {
    int lo = 0, hi = n;
    while (lo < hi) { int mid = (lo + hi) >> 1; if (arr[mid] < val) lo = mid + 1; else hi = mid; }
    return lo;
}

__global__ void k_vt(const float* __restrict__ hl, const int* __restrict__ batch,
                     const float* __restrict__ vn, float* __restrict__ vt) {
    int g = blockIdx.x;
    __shared__ int ss, se;
    if (threadIdx.x == 0) { ss = lbound(batch, NN, g); se = lbound(batch, NN, g + 1); }
    __syncthreads();
    int s0 = ss, s1 = se;
    for (int c = threadIdx.x; c < DD; c += blockDim.x) {
        float s = vn[(size_t)g * DD + c];
        for (int r = s0; r < s1; r++) s += hl[(size_t)r * DD + c];
        vt[(size_t)g * DD + c] = s;
    }
}

__global__ void k_pool(const float* __restrict__ h, const int* __restrict__ batch,
                       const float* __restrict__ fp, float* __restrict__ hg) {
    int g = blockIdx.x;
    __shared__ int ss, se;
    if (threadIdx.x == 0) { ss = lbound(batch, NN, g); se = lbound(batch, NN, g + 1); }
    __syncthreads();
    int s0 = ss, s1 = se;
    for (int c = threadIdx.x; c < HGC; c += blockDim.x) {
        float v;
        if (c < DD) {
            v = 0.f;
            for (int r = s0; r < s1; r++) v += h[(size_t)r * DD + c];
        } else {
            v = fp[(size_t)g * 2048 + (c - DD)];
        }
        hg[(size_t)g * HGC + c] = v;
    }
}

__global__ void k_bnfinal(const float* __restrict__ stats,
                          const float* __restrict__ gamma,
                          const float* __restrict__ beta,
                          int M, int C,
                          float* __restrict__ scale, float* __restrict__ shift) {
    int c = blockIdx.x * blockDim.x + threadIdx.x;
    if (c >= C) return;
    float inv = 1.f / (float)M;
    float mean = stats[c] * inv;
    float var  = stats[C + c] * inv - mean * mean;
    float s = gamma[c] * rsqrtf(var + 1e-5f);
    scale[c] = s;
    shift[c] = beta[c] - mean * s;
}

__global__ void k_bnapply(const float* __restrict__ X, float* __restrict__ Y,
                          size_t total4, int C4,
                          const float* __restrict__ scale,
                          const float* __restrict__ shift, int relu) {
    size_t idx4 = (size_t)blockIdx.x * blockDim.x + threadIdx.x;
    if (idx4 >= total4) return;
    int c4 = (int)(idx4 % C4) * 4;
    float4 x = ((const float4*)X)[idx4];
    float4 o;
    o.x = x.x * scale[c4 + 0] + shift[c4 + 0];
    o.y = x.y * scale[c4 + 1] + shift[c4 + 1];
    o.z = x.z * scale[c4 + 2] + shift[c4 + 2];
    o.w = x.w * scale[c4 + 3] + shift[c4 + 3];
    if (relu) {
        o.x = fmaxf(o.x, 0.f); o.y = fmaxf(o.y, 0.f);
        o.z = fmaxf(o.z, 0.f); o.w = fmaxf(o.w, 0.f);
    }
    ((float4*)Y)[idx4] = o;
}

// ---------------- bf16-split (bf16x3) tensor-core GEMM ----------------
__device__ __forceinline__ uint32_t packbf2(float a, float b) {
    __nv_bfloat162 t = __floats2bfloat162_rn(a, b);
    return *reinterpret_cast<uint32_t*>(&t);
}
__device__ __forceinline__ float bf_hi(float x) {
    return __bfloat162float(__float2bfloat16_rn(x));
}

__device__ __forceinline__ void mma_bf16(float* d, const uint32_t* a, const uint32_t* b) {
    asm volatile(
        "mma.sync.aligned.m16n8k16.row.col.f32.bf16.bf16.f32 "
        "{%0,%1,%2,%3}, {%4,%5,%6,%7}, {%8,%9}, {%0,%1,%2,%3};\n"
        : "+f"(d[0]), "+f"(d[1]), "+f"(d[2]), "+f"(d[3])
        : "r"(a[0]), "r"(a[1]), "r"(a[2]), "r"(a[3]),
          "r"(b[0]), "r"(b[1]));
}

__device__ __forceinline__ float gelu_tanh(float x) {
    const float k0 = 0.7978845608028654f;
    const float k1 = 0.044715f;
    float x3 = x * x * x;
    return 0.5f * x * (1.f + tanhf(k0 * (x + k1 * x3)));
}

#define SMP 136

__global__ __launch_bounds__(256, 2)
void k_mma(int M, int N, int K,
           const float* __restrict__ A, const float* __restrict__ B,
           const float* __restrict__ bias, float* __restrict__ C,
           const float* __restrict__ aScale, const float* __restrict__ aShift,
           float* stats, int act) {
    __shared__ __align__(16) uint32_t AsH[2][8][SMP];
    __shared__ __align__(16) uint32_t AsL[2][8][SMP];
    __shared__ __align__(16) uint32_t BsH[2][8][SMP];
    __shared__ __align__(16) uint32_t BsL[2][8][SMP];

    const int tid  = threadIdx.x;
    const int lane = tid & 31;
    const int warp = tid >> 5;
    const int warpM = warp >> 2;
    const int warpN = warp & 3;
    const int gID = lane >> 2;
    const int tg  = lane & 3;
    const int rowBase = blockIdx.y * 128;
    const int colBase = blockIdx.x * 128;
    const bool aTrans = (aScale != nullptr);

    float acc[4][4][4];
    #pragma unroll
    for (int i = 0; i < 4; i++)
        #pragma unroll
        for (int j = 0; j < 4; j++)
            #pragma unroll
            for (int r = 0; r < 4; r++) acc[i][j][r] = 0.f;

    const int KT = (K + 15) / 16;

    float4 aV[2];
    float4 bV0, bV1;
    const int bKp  = tid >> 5;
    const int bC4  = tid & 31;

    auto loadTile = [&](int t) {
        int k0 = t * 16;
        #pragma unroll
        for (int i = 0; i < 2; i++) {
            int tl = tid + i * 256;
            int row = tl >> 2, c4 = tl & 3;
            int gk = k0 + c4 * 4;
            float4 v = make_float4(0.f, 0.f, 0.f, 0.f);
            if (gk < K) {
                v = *(const float4*)(A + (size_t)(rowBase + row) * K + gk);
                if (aTrans) {
                    v.x = fmaxf(v.x * __ldg(aScale + gk + 0) + __ldg(aShift + gk + 0), 0.f);
                    v.y = fmaxf(v.y * __ldg(aScale + gk + 1) + __ldg(aShift + gk + 1), 0.f);
                    v.z = fmaxf(v.z * __ldg(aScale + gk + 2) + __ldg(aShift + gk + 2), 0.f);
                    v.w = fmaxf(v.w * __ldg(aScale + gk + 3) + __ldg(aShift + gk + 3), 0.f);
                }
            }
            aV[i] = v;
        }
        int gr0 = k0 + 2 * bKp;
        int gc  = colBase + bC4 * 4;
        bV0 = make_float4(0.f, 0.f, 0.f, 0.f);
        bV1 = make_float4(0.f, 0.f, 0.f, 0.f);
        if (gc < N) {
            if (gr0     < K) bV0 = *(const float4*)(B + (size_t)gr0       * N + gc);
            if (gr0 + 1 < K) bV1 = *(const float4*)(B + (size_t)(gr0 + 1) * N + gc);
        }
    };

    auto storeTile = [&](int buf) {
        #pragma unroll
        for (int i = 0; i < 2; i++) {
            int tl = tid + i * 256;
            int row = tl >> 2, c4 = tl & 3;
            float4 v = aV[i];
            float hx = bf_hi(v.x), hy = bf_hi(v.y), hz = bf_hi(v.z), hw = bf_hi(v.w);
            AsH[buf][c4 * 2    ][row] = packbf2(hx, hy);
            AsH[buf][c4 * 2 + 1][row] = packbf2(hz, hw);
            AsL[buf][c4 * 2    ][row] = packbf2(v.x - hx, v.y - hy);
            AsL[buf][c4 * 2 + 1][row] = packbf2(v.z - hz, v.w - hw);
        }
        float h0x = bf_hi(bV0.x), h0y = bf_hi(bV0.y), h0z = bf_hi(bV0.z), h0w = bf_hi(bV0.w);
        float h1x = bf_hi(bV1.x), h1y = bf_hi(bV1.y), h1z = bf_hi(bV1.z), h1w = bf_hi(bV1.w);
        uint4 hv = make_uint4(packbf2(h0x, h1x), packbf2(h0y, h1y),
                              packbf2(h0z, h1z), packbf2(h0w, h1w));
        uint4 lv = make_uint4(packbf2(bV0.x - h0x, bV1.x - h1x),
                              packbf2(bV0.y - h0y, bV1.y - h1y),
                              packbf2(bV0.z - h0z, bV1.z - h1z),
                              packbf2(bV0.w - h0w, bV1.w - h1w));
        *(uint4*)&BsH[buf][bKp][bC4 * 4] = hv;
        *(uint4*)&BsL[buf][bKp][bC4 * 4] = lv;
    };

    loadTile(0);
    storeTile(0);
    __syncthreads();

    for (int t = 0; t < KT; t++) {
        int buf = t & 1;
        if (t + 1 < KT) loadTile(t + 1);

        uint32_t bh[4][2], bl[4][2];
        #pragma unroll
        for (int nt = 0; nt < 4; nt++) {
            int c = warpN * 32 + nt * 8 + gID;
            bh[nt][0] = BsH[buf][tg    ][c];
            bh[nt][1] = BsH[buf][tg + 4][c];
            bl[nt][0] = BsL[buf][tg    ][c];
            bl[nt][1] = BsL[buf][tg + 4][c];
        }
        #pragma unroll
        for (int mt = 0; mt < 4; mt++) {
            int r0 = warpM * 64 + mt * 16 + gID;
            uint32_t ah[4], al[4];
            ah[0] = AsH[buf][tg    ][r0];
            ah[1] = AsH[buf][tg    ][r0 + 8];
            ah[2] = AsH[buf][tg + 4][r0];
            ah[3] = AsH[buf][tg + 4][r0 + 8];
            al[0] = AsL[buf][tg    ][r0];
            al[1] = AsL[buf][tg    ][r0 + 8];
            al[2] = AsL[buf][tg + 4][r0];
            al[3] = AsL[buf][tg + 4][r0 + 8];
            #pragma unroll
            for (int nt = 0; nt < 4; nt++) {
                mma_bf16(acc[mt][nt], ah, bh[nt]);
                mma_bf16(acc[mt][nt], ah, bl[nt]);
                mma_bf16(acc[mt][nt], al, bh[nt]);
            }
        }

        if (t + 1 < KT) storeTile(buf ^ 1);
        __syncthreads();
    }

    // ---- epilogue ----
    const bool doStats = (stats != nullptr);
    float* sstat = reinterpret_cast<float*>(&AsH[0][0][0]);
    if (doStats) {
        if (tid < 256) sstat[tid] = 0.f;
        __syncthreads();
    }

    #pragma unroll
    for (int nt = 0; nt < 4; nt++) {
        #pragma unroll
        for (int p = 0; p < 2; p++) {
            int lc = warpN * 32 + nt * 8 + 2 * tg + p;
            int col = colBase + lc;
            bool cv = col < N;
            float bs = cv ? __ldg(bias + col) : 0.f;
            float s = 0.f, s2 = 0.f;
            #pragma unroll
            for (int mt = 0; mt < 4; mt++) {
                int row = rowBase + warpM * 64 + mt * 16 + gID;
                #pragma unroll
                for (int hh = 0; hh < 2; hh++) {
                    float v = acc[mt][nt][p + 2 * hh] + bs;
                    s += v; s2 += v * v;
                    float o = v;
                    if (act == 1) o = fmaxf(o, 0.f);
                    else if (act == 2) o = gelu_tanh(o);
                    if (cv) C[(size_t)(row + 8 * hh) * N + col] = o;
                }
            }
            if (doStats && cv) {
                atomicAdd(&sstat[lc], s);
                atomicAdd(&sstat[128 + lc], s2);
            }
        }
    }
    if (doStats) {
        __syncthreads();
        if (tid < 128) {
            int col = colBase + tid;
            if (col < N) {
                atomicAdd(&stats[col], sstat[tid]);
                atomicAdd(&stats[N + col], sstat[128 + tid]);
            }
        }
    }
}

// ---------------- host orchestration ----------------
static inline int cdiv(long long a, long long b) { return (int)((a + b - 1) / b); }

static void launch_mma(int M, int N, int K, const float* A, const float* B,
                       const float* bias, float* C,
                       const float* aS, const float* aH, float* stats, int act) {
    dim3 grid(cdiv(N, 128), M / 128);
    k_mma<<<grid, 256>>>(M, N, K, A, B, bias, C, aS, aH, stats, act);
}

extern "C" void kernel_launch(void* const* d_in, const int* in_sizes, int n_in,
                              void* d_out, int out_size) {
    const int*   x_atom  = (const int*)  d_in[0];
    const int*   src     = (const int*)  d_in[1];
    const int*   dst     = (const int*)  d_in[2];
    const int*   eattr   = (const int*)  d_in[3];
    const int*   batch   = (const int*)  d_in[4];
    const float* fp      = (const float*)d_in[5];
    const float* atom_emb= (const float*)d_in[6];
    const float* edge_emb= (const float*)d_in[7];
    const float* eps     = (const float*)d_in[8];
    const float* W1  = (const float*)d_in[9];
    const float* b1  = (const float*)d_in[10];
    const float* g1  = (const float*)d_in[11];
    const float* be1 = (const float*)d_in[12];
    const float* W2  = (const float*)d_in[13];
    const float* b2  = (const float*)d_in[14];
    const float* bng = (const float*)d_in[15];
    const float* bnb = (const float*)d_in[16];
    const float* vW1 = (const float*)d_in[17];
    const float* vb1 = (const float*)d_in[18];
    const float* vg1 = (const float*)d_in[19];
    const float* vbe1= (const float*)d_in[20];
    const float* vW2 = (const float*)d_in[21];
    const float* vb2 = (const float*)d_in[22];
    const float* vg2 = (const float*)d_in[23];
    const float* vbe2= (const float*)d_in[24];
    const float* pW1 = (const float*)d_in[25];
    const float* pb1 = (const float*)d_in[26];
    const float* pW2 = (const float*)d_in[27];
    const float* pb2 = (const float*)d_in[28];
    float* out = (float*)d_out;

    float *p_h, *p_hl, *p_acc, *p_y1, *p_y2, *p_vn, *p_vt, *p_u1, *p_u2,
          *p_hg, *p_t1, *p_stats, *p_scale, *p_shift;
    cudaGetSymbolAddress((void**)&p_h,    g_h);
    cudaGetSymbolAddress((void**)&p_hl,   g_hl);
    cudaGetSymbolAddress((void**)&p_acc,  g_acc);
    cudaGetSymbolAddress((void**)&p_y1,   g_y1);
    cudaGetSymbolAddress((void**)&p_y2,   g_y2);
    cudaGetSymbolAddress((void**)&p_vn,   g_vn);
    cudaGetSymbolAddress((void**)&p_vt,   g_vt);
    cudaGetSymbolAddress((void**)&p_u1,   g_u1);
    cudaGetSymbolAddress((void**)&p_u2,   g_u2);
    cudaGetSymbolAddress((void**)&p_hg,   g_hg);
    cudaGetSymbolAddress((void**)&p_t1,   g_t1);
    cudaGetSymbolAddress((void**)&p_stats,g_stats);
    cudaGetSymbolAddress((void**)&p_scale,g_scale);
    cudaGetSymbolAddress((void**)&p_shift,g_shift);

    const size_t ND  = (size_t)NN * DD;
    const size_t GD  = (size_t)GG * DD;
    const size_t ND4 = ND / 4;

    k_zero<<<cdiv(GD, 256), 256>>>(p_vn, GD);                        // launch 1
    k_embed<<<cdiv(ND4, 256), 256>>>(x_atom, atom_emb, p_h);         // launch 2

    for (int l = 0; l < LL; l++) {
        int doVt = (l < LL - 1);

        // Ordered so that ncu (-s 5 -c 1) captures GEMM1 (launch #6 on l==0).
        k_hl_acc<<<cdiv(ND4, 256), 256>>>(p_h, p_vn, batch, eps, l, p_hl, p_acc);  // 3
        k_zero<<<cdiv(2 * DD2, 256), 256>>>(p_stats, 2 * DD2);                     // 4
        k_edge<<<EE / 4, 300>>>(p_hl, edge_emb + (size_t)l * 5 * DD,
                                src, dst, eattr, p_acc);                           // 5
        launch_mma(NN, DD2, DD, p_acc, W1 + (size_t)l * DD * DD2,
                   b1 + (size_t)l * DD2, p_y1, nullptr, nullptr, p_stats, 0);      // 6 (GEMM1)

        if (doVt)
            k_vt<<<GG, 128>>>(p_hl, batch, p_vn, p_vt);

        k_bnfinal<<<cdiv(DD2, 256), 256>>>(p_stats, g1 + (size_t)l * DD2,
                                           be1 + (size_t)l * DD2, NN, DD2,
                                           p_scale, p_shift);

        // GEMM2: relu(bn(y1)) @ W2 (+stats); BN fused on A-load
        k_zero<<<cdiv(2 * DD, 256), 256>>>(p_stats, 2 * DD);
        launch_mma(NN, DD, DD2, p_y1, W2 + (size_t)l * DD2 * DD,
                   b2 + (size_t)l * DD, p_y2, p_scale, p_shift, p_stats, 0);
        k_bnfinal<<<cdiv(DD, 256), 256>>>(p_stats, bng + (size_t)l * DD,
                                          bnb + (size_t)l * DD, NN, DD,
                                          p_scale, p_shift);
        k_bnapply<<<cdiv(ND4, 256), 256>>>(p_y2, p_h, ND4, DD / 4,
                                           p_scale, p_shift, doVt ? 1 : 0);

        if (doVt) {
            k_zero<<<cdiv(2 * DD2, 256), 256>>>(p_stats, 2 * DD2);
            launch_mma(GG, DD2, DD, p_vt, vW1 + (size_t)l * DD * DD2,
                       vb1 + (size_t)l * DD2, p_u1, nullptr, nullptr, p_stats, 0);
            k_bnfinal<<<cdiv(DD2, 256), 256>>>(p_stats, vg1 + (size_t)l * DD2,
                                               vbe1 + (size_t)l * DD2, GG, DD2,
                                               p_scale, p_shift);

            k_zero<<<cdiv(2 * DD, 256), 256>>>(p_stats, 2 * DD);
            launch_mma(GG, DD, DD2, p_u1, vW2 + (size_t)l * DD2 * DD,
                       vb2 + (size_t)l * DD, p_u2, p_scale, p_shift, p_stats, 0);
            k_bnfinal<<<cdiv(DD, 256), 256>>>(p_stats, vg2 + (size_t)l * DD,
                                              vbe2 + (size_t)l * DD, GG, DD,
                                              p_scale, p_shift);
            k_bnapply<<<cdiv(GD / 4, 256), 256>>>(p_u2, p_vn, GD / 4, DD / 4,
                                                  p_scale, p_shift, 1);
        }
    }

    // head
    k_pool<<<GG, 256>>>(p_h, batch, fp, p_hg);
    launch_mma(GG, H1, HGC, p_hg, pW1, pb1, p_t1, nullptr, nullptr, nullptr, 2);
    launch_mma(GG, NT, H1, p_t1, pW2, pb2, out, nullptr, nullptr, nullptr, 0);
}